// round 2
// baseline (speedup 1.0000x reference)
#include <cuda_runtime.h>
#include <cuda_bf16.h>

#define B_SZ   16
#define SEQ    2048
#define EMBED  128
#define DSTATE 16
#define HID    256
#define NCLS   10
#define NEDGE  8192
#define KLEN   64
#define NROW   (B_SZ*SEQ)   // 32768

// ---------------- scratch (static device arrays; no allocation) ----------------
__device__ float g_x[NROW*EMBED];          // (B,SEQ,EMBED)  16.8MB
__device__ float g_bmat[B_SZ*DSTATE*SEQ];  // [b][d][t]       2.1MB
__device__ float g_conv[NROW*DSTATE];      // [b][t][d]       2.1MB
__device__ float g_h[NROW*EMBED];          // LN output      16.8MB
__device__ float g_hagg[NROW*EMBED];       // scatter accum  16.8MB
__device__ float g_wT[256*256];            // combined weight, [k][h] transposed
__device__ float g_K[DSTATE*KLEN];         // conv taps
__device__ float g_pooled[B_SZ*HID];       // pooled partials

// ---------------- zero scratch that is accumulated into ----------------
__global__ void k_zero() {
    int i = blockIdx.x * blockDim.x + threadIdx.x;   // 4096*256 = 1048576
    float4 z = make_float4(0.f, 0.f, 0.f, 0.f);
    ((float4*)g_hagg)[i] = z;
    if (i < (B_SZ*HID)/4) ((float4*)g_pooled)[i] = z;
}

// ---------------- conv taps: K[d][tau] = mean_e Aexp[e,d]^tau ----------------
__global__ void k_prep(const float* __restrict__ A_log) {
    int d = blockIdx.x;            // 16 blocks
    int tid = threadIdx.x;         // 128 threads (= e)
    float a = expf(-expf(A_log[tid*DSTATE + d]));
    float p = 1.f;
    __shared__ float ws[4];
    for (int tau = 0; tau < KLEN; tau++) {
        float s = p;
        for (int o = 16; o; o >>= 1) s += __shfl_down_sync(0xffffffffu, s, o);
        if ((tid & 31) == 0) ws[tid >> 5] = s;
        __syncthreads();
        if (tid == 0) g_K[d*KLEN + tau] = (ws[0]+ws[1]+ws[2]+ws[3]) * (1.f/128.f);
        __syncthreads();
        p *= a;
    }
}

// ---------------- combined weight: wT[k][h] = [Wupd1 | Wupd2@Wmsg] ----------------
__global__ void k_wcomb(const float* __restrict__ Wupd_w, const float* __restrict__ Wmsg_w) {
    int k = blockIdx.x;     // 256
    int h = threadIdx.x;    // 256
    float v;
    if (k < 128) {
        v = Wupd_w[h*384 + k];
    } else {
        int d = k - 128;
        float acc = 0.f;
        const float* w2 = Wupd_w + h*384 + 128;
        for (int hp = 0; hp < 256; hp++) acc += w2[hp] * Wmsg_w[hp*128 + d];
        v = acc;
    }
    g_wT[k*256 + h] = v;
}

// ---------------- embedding gather + B projection ----------------
__global__ void k_embed(const int* __restrict__ tokens, const float* __restrict__ emb,
                        const float* __restrict__ B_w) {
    int row = blockIdx.x;          // 32768
    int tid = threadIdx.x;         // 128
    int tok = tokens[row];
    float xe = emb[tok*EMBED + tid];
    g_x[row*EMBED + tid] = xe;
    __shared__ float sx[EMBED];
    sx[tid] = xe;
    __syncthreads();
    int d = tid >> 3, p = tid & 7;
    float acc = 0.f;
    const float* bw = B_w + d*EMBED + p*16;
    const float* xs = sx + p*16;
#pragma unroll
    for (int e = 0; e < 16; e++) acc += bw[e] * xs[e];
    acc += __shfl_down_sync(0xffffffffu, acc, 4, 8);
    acc += __shfl_down_sync(0xffffffffu, acc, 2, 8);
    acc += __shfl_down_sync(0xffffffffu, acc, 1, 8);
    if (p == 0) {
        int b = row >> 11, t = row & (SEQ-1);
        g_bmat[(b*DSTATE + d)*SEQ + t] = acc;
    }
}

// ---------------- 64-tap causal convolution ----------------
__global__ void k_conv() {
    int bd = blockIdx.x;           // 256 = B*DSTATE
    int b = bd >> 4, d = bd & 15;
    __shared__ float sK[KLEN];
    int tid = threadIdx.x;         // 256
    if (tid < KLEN) sK[tid] = g_K[d*KLEN + tid];
    __syncthreads();
    const float* bm = g_bmat + bd*SEQ;
    for (int t0 = tid; t0 < SEQ; t0 += 256) {
        float acc = 0.f;
        int tmax = t0 < (KLEN-1) ? t0 : (KLEN-1);
        for (int tau = 0; tau <= tmax; tau++) acc += sK[tau] * bm[t0 - tau];
        g_conv[(b*SEQ + t0)*DSTATE + d] = acc;
    }
}

// ---------------- y = conv@C^T + D*x, then LayerNorm ----------------
__global__ void k_yln(const float* __restrict__ C_w, const float* __restrict__ Dskip,
                      const float* __restrict__ ln_g, const float* __restrict__ ln_b) {
    int row = blockIdx.x;          // 32768
    int tid = threadIdx.x;         // 128
    __shared__ float scv[DSTATE];
    __shared__ float ws[4], ws2[4];
    if (tid < DSTATE) scv[tid] = g_conv[row*DSTATE + tid];
    __syncthreads();
    float y = Dskip[tid] * g_x[row*EMBED + tid];
#pragma unroll
    for (int dd = 0; dd < DSTATE; dd++) y += scv[dd] * C_w[tid*DSTATE + dd];
    float s = y, s2 = y*y;
    for (int o = 16; o; o >>= 1) {
        s  += __shfl_down_sync(0xffffffffu, s,  o);
        s2 += __shfl_down_sync(0xffffffffu, s2, o);
    }
    int w = tid >> 5, l = tid & 31;
    if (l == 0) { ws[w] = s; ws2[w] = s2; }
    __syncthreads();
    float mu  = (ws[0]+ws[1]+ws[2]+ws[3])  * (1.f/128.f);
    float m2  = (ws2[0]+ws2[1]+ws2[2]+ws2[3]) * (1.f/128.f);
    float var = m2 - mu*mu;
    g_h[row*EMBED + tid] = ln_g[tid] * (y - mu) * rsqrtf(var + 1e-5f) + ln_b[tid];
}

// ---------------- edge scatter: hagg[b,dst] += h[b,src] ----------------
__global__ void k_scatter(const int* __restrict__ ei) {
    int widx = (blockIdx.x * blockDim.x + threadIdx.x) >> 5;  // warp per edge
    int lane = threadIdx.x & 31;
    int b  = widx >> 13;            // /NEDGE
    int el = widx & (NEDGE-1);
    const int* eb = ei + b*2*NEDGE;
    int src = eb[el];
    int dst = eb[NEDGE + el];
    const float4* hs = (const float4*)(g_h + (b*SEQ + src)*EMBED);
    float* ha = g_hagg + (b*SEQ + dst)*EMBED;
    float4 v = hs[lane];
    atomicAdd(ha + lane*4 + 0, v.x);
    atomicAdd(ha + lane*4 + 1, v.y);
    atomicAdd(ha + lane*4 + 2, v.z);
    atomicAdd(ha + lane*4 + 3, v.w);
}

// ---------------- fused update GEMM + relu + mean-pool ----------------
// A = [h | hagg] (32768 x 256), W' = g_wT (256k x 256h). Each CTA: 64 rows x 256 cols.
__global__ __launch_bounds__(256, 2)
void k_updpool(const float* __restrict__ Wupd_b) {
    __shared__ float Ast[32][68];      // [k][row], padded (68*4 bytes, 16B-aligned rows)
    __shared__ float Ws[32][256];      // [k][h]
    int r0 = blockIdx.x * 64;          // 512 blocks
    int b  = r0 >> 11;
    int tid = threadIdx.x;
    int ty = tid >> 5;                 // 0..7  (row group)
    int tx = tid & 31;                 // 0..31 (col group)
    float acc[8][8];
#pragma unroll
    for (int i = 0; i < 8; i++)
#pragma unroll
        for (int j = 0; j < 8; j++) acc[i][j] = 0.f;

    for (int kt = 0; kt < 256; kt += 32) {
        const float* Asrc = (kt < 128) ? (g_h + r0*EMBED + kt)
                                       : (g_hagg + r0*EMBED + (kt - 128));
#pragma unroll
        for (int it = 0; it < 2; it++) {
            int fid = tid + it*256;        // 0..511 float4s
            int r  = fid >> 3;
            int kq = fid & 7;
            float4 v = *(const float4*)(Asrc + r*EMBED + kq*4);
            Ast[kq*4+0][r] = v.x; Ast[kq*4+1][r] = v.y;
            Ast[kq*4+2][r] = v.z; Ast[kq*4+3][r] = v.w;
        }
#pragma unroll
        for (int it = 0; it < 8; it++) {
            int fid = tid + it*256;        // 0..2047 float4s
            int kk = fid >> 6;
            int hq = fid & 63;
            *(float4*)&Ws[kk][hq*4] = *(const float4*)(g_wT + (kt+kk)*256 + hq*4);
        }
        __syncthreads();
#pragma unroll
        for (int kk = 0; kk < 32; kk++) {
            float a[8], w[8];
            *(float4*)(a)   = *(const float4*)&Ast[kk][ty*8];
            *(float4*)(a+4) = *(const float4*)&Ast[kk][ty*8+4];
#pragma unroll
            for (int j = 0; j < 8; j++) w[j] = Ws[kk][tx + 32*j];
#pragma unroll
            for (int i = 0; i < 8; i++)
#pragma unroll
                for (int j = 0; j < 8; j++) acc[i][j] += a[i] * w[j];
        }
        __syncthreads();
    }
    // epilogue: bias, relu, sum rows, block-reduce, atomic to pooled
    float colsum[8];
#pragma unroll
    for (int j = 0; j < 8; j++) {
        float bias = Wupd_b[tx + 32*j];
        float s = 0.f;
#pragma unroll
        for (int i = 0; i < 8; i++) s += fmaxf(acc[i][j] + bias, 0.f);
        colsum[j] = s;
    }
    float* red = &Ws[0][0];
#pragma unroll
    for (int j = 0; j < 8; j++) red[ty*256 + tx + 32*j] = colsum[j];
    __syncthreads();
    if (ty == 0) {
#pragma unroll
        for (int j = 0; j < 8; j++) {
            int col = tx + 32*j;
            float s = 0.f;
#pragma unroll
            for (int g = 0; g < 8; g++) s += red[g*256 + col];
            atomicAdd(&g_pooled[b*HID + col], s);
        }
    }
}

// ---------------- classifier ----------------
__global__ void k_cls(const float* __restrict__ cls_w, const float* __restrict__ cls_b,
                      float* __restrict__ out) {
    int tid = threadIdx.x;
    if (tid >= B_SZ*NCLS) return;
    int b = tid / NCLS, c = tid % NCLS;
    float acc = 0.f;
    const float* p = g_pooled + b*HID;
    const float* w = cls_w + c*HID;
    for (int h = 0; h < HID; h++) acc += p[h] * w[h];
    out[b*NCLS + c] = cls_b[c] + acc * (1.f/(float)SEQ);
}

// ---------------- launch ----------------
extern "C" void kernel_launch(void* const* d_in, const int* in_sizes, int n_in,
                              void* d_out, int out_size) {
    const int*   tokens = (const int*)  d_in[0];
    // d_in[1] = lengths (unused by reference)
    const int*   ei     = (const int*)  d_in[2];
    const float* emb    = (const float*)d_in[3];
    const float* A_log  = (const float*)d_in[4];
    const float* B_w    = (const float*)d_in[5];
    const float* C_w    = (const float*)d_in[6];
    const float* Dskip  = (const float*)d_in[7];
    const float* ln_g   = (const float*)d_in[8];
    const float* ln_b   = (const float*)d_in[9];
    const float* Wmsg   = (const float*)d_in[10];
    const float* Wupd   = (const float*)d_in[11];
    const float* Wupd_b = (const float*)d_in[12];
    const float* cls_w  = (const float*)d_in[13];
    const float* cls_b  = (const float*)d_in[14];
    float* out = (float*)d_out;

    k_zero  <<<4096, 256>>>();
    k_prep  <<<DSTATE, 128>>>(A_log);
    k_wcomb <<<256, 256>>>(Wupd, Wmsg);
    k_embed <<<NROW, 128>>>(tokens, emb, B_w);
    k_conv  <<<B_SZ*DSTATE, 256>>>();
    k_yln   <<<NROW, 128>>>(C_w, Dskip, ln_g, ln_b);
    k_scatter<<<(B_SZ*NEDGE*32)/256, 256>>>(ei);
    k_updpool<<<NROW/64, 256>>>(Wupd_b);
    k_cls   <<<1, 256>>>(cls_w, cls_b, out);
}

// round 3
// speedup vs baseline: 1.3623x; 1.3623x over previous
#include <cuda_runtime.h>
#include <cuda_bf16.h>

#define B_SZ   16
#define SEQ    2048
#define EMBED  128
#define DSTATE 16
#define HID    256
#define NCLS   10
#define NEDGE  8192
#define KLEN   64
#define NROW   (B_SZ*SEQ)   // 32768

// ---------------- scratch (static device arrays; no allocation) ----------------
__device__ float g_bmat[B_SZ*DSTATE*SEQ];  // [b][d][t]       2.1MB
__device__ float g_conv[NROW*DSTATE];      // [b][t][d]       2.1MB
__device__ float g_h[NROW*EMBED];          // LN output      16.8MB
__device__ float g_hagg[NROW*EMBED];       // gathered msgs  16.8MB
__device__ float g_wT[256*256];            // combined weight [k][h]
__device__ float g_K[DSTATE*KLEN];         // conv taps
__device__ float g_pooled[B_SZ*HID];       // pooled partials
__device__ int   g_cnt[NROW];              // edges per dst node
__device__ int   g_off[NROW];              // CSR offsets (per batch)
__device__ int   g_cur[NROW];              // fill cursors
__device__ int   g_srcs[B_SZ*NEDGE];       // CSR src lists

// ---------------- zero counters / accumulators ----------------
__global__ void k_zero() {
    int i = blockIdx.x * blockDim.x + threadIdx.x;   // 128*256 = 32768
    g_cnt[i] = 0;
    g_cur[i] = 0;
    if (i < B_SZ*HID) g_pooled[i] = 0.f;
}

// ---------------- conv taps: K[d][tau] = mean_e Aexp[e,d]^tau ----------------
__global__ void k_prep(const float* __restrict__ A_log) {
    int d = blockIdx.x;            // 16 blocks
    int tid = threadIdx.x;         // 128 threads (= e)
    float a = expf(-expf(A_log[tid*DSTATE + d]));
    float p = 1.f;
    __shared__ float ws[4];
    for (int tau = 0; tau < KLEN; tau++) {
        float s = p;
        for (int o = 16; o; o >>= 1) s += __shfl_down_sync(0xffffffffu, s, o);
        if ((tid & 31) == 0) ws[tid >> 5] = s;
        __syncthreads();
        if (tid == 0) g_K[d*KLEN + tau] = (ws[0]+ws[1]+ws[2]+ws[3]) * (1.f/128.f);
        __syncthreads();
        p *= a;
    }
}

// ---------------- combined weight: wT[k][h] = [Wupd1 | Wupd2@Wmsg] ----------------
__global__ void k_wcomb(const float* __restrict__ Wupd_w, const float* __restrict__ Wmsg_w) {
    int k = blockIdx.x;     // 256
    int h = threadIdx.x;    // 256
    float v;
    if (k < 128) {
        v = Wupd_w[h*384 + k];
    } else {
        int d = k - 128;
        float acc = 0.f;
        const float* w2 = Wupd_w + h*384 + 128;
        for (int hp = 0; hp < 256; hp++) acc += w2[hp] * Wmsg_w[hp*128 + d];
        v = acc;
    }
    g_wT[k*256 + h] = v;
}

// ---------------- B projection: bmat[b][d][t] = emb[tok]·B_w[d] ----------------
// Warp per 8 consecutive rows. Lane = (d, half): B_w half held in 16 float4 regs.
__global__ void k_bproj(const int* __restrict__ tokens, const float* __restrict__ emb,
                        const float* __restrict__ B_w) {
    int w = (blockIdx.x * blockDim.x + threadIdx.x) >> 5;   // 0..4095
    int lane = threadIdx.x & 31;
    int d = lane >> 1, kg = lane & 1;
    float4 wr[16];
    const float4* bw = (const float4*)(B_w + d*EMBED + kg*64);
#pragma unroll
    for (int i = 0; i < 16; i++) wr[i] = bw[i];
    int r0 = w * 8;
    int b = r0 >> 11, t0 = r0 & (SEQ-1);
    float vals[8];
#pragma unroll
    for (int j = 0; j < 8; j++) {
        int tok = tokens[r0 + j];
        const float4* xp = (const float4*)(emb + tok*EMBED + kg*64);
        float acc = 0.f;
#pragma unroll
        for (int i = 0; i < 16; i++) {
            float4 x = xp[i];
            acc += wr[i].x*x.x + wr[i].y*x.y + wr[i].z*x.z + wr[i].w*x.w;
        }
        acc += __shfl_xor_sync(0xffffffffu, acc, 1);
        vals[j] = acc;
    }
    if (kg == 0) {
        float* bp = g_bmat + (b*DSTATE + d)*SEQ + t0;
        *(float4*)(bp)   = make_float4(vals[0], vals[1], vals[2], vals[3]);
        *(float4*)(bp+4) = make_float4(vals[4], vals[5], vals[6], vals[7]);
    }
}

// ---------------- 64-tap causal convolution (smem-staged) ----------------
__global__ void k_conv() {
    int bd = blockIdx.x;           // 256 = B*DSTATE
    int b = bd >> 4, d = bd & 15;
    __shared__ float sb[SEQ];      // 8KB
    __shared__ float sK[KLEN];
    int tid = threadIdx.x;         // 256
    if (tid < KLEN) sK[tid] = g_K[d*KLEN + tid];
    const float4* bm4 = (const float4*)(g_bmat + bd*SEQ);
    float4* sb4 = (float4*)sb;
    for (int i = tid; i < SEQ/4; i += 256) sb4[i] = bm4[i];
    __syncthreads();
    for (int t0 = tid; t0 < SEQ; t0 += 256) {
        float acc = 0.f;
        int tmax = t0 < (KLEN-1) ? t0 : (KLEN-1);
        for (int tau = 0; tau <= tmax; tau++) acc += sK[tau] * sb[t0 - tau];
        g_conv[(b*SEQ + t0)*DSTATE + d] = acc;
    }
}

// ---------------- y = conv@C^T + D*emb[tok], then LayerNorm ----------------
__global__ void k_yln(const int* __restrict__ tokens, const float* __restrict__ emb,
                      const float* __restrict__ C_w, const float* __restrict__ Dskip,
                      const float* __restrict__ ln_g, const float* __restrict__ ln_b) {
    int row = blockIdx.x;          // 32768
    int tid = threadIdx.x;         // 128
    __shared__ float scv[DSTATE];
    __shared__ float ws[4], ws2[4];
    if (tid < DSTATE) scv[tid] = g_conv[row*DSTATE + tid];
    __syncthreads();
    int tok = tokens[row];
    float xe = emb[tok*EMBED + tid];
    float y = Dskip[tid] * xe;
#pragma unroll
    for (int dd = 0; dd < DSTATE; dd++) y += scv[dd] * C_w[tid*DSTATE + dd];
    float s = y, s2 = y*y;
    for (int o = 16; o; o >>= 1) {
        s  += __shfl_down_sync(0xffffffffu, s,  o);
        s2 += __shfl_down_sync(0xffffffffu, s2, o);
    }
    int w = tid >> 5, l = tid & 31;
    if (l == 0) { ws[w] = s; ws2[w] = s2; }
    __syncthreads();
    float mu  = (ws[0]+ws[1]+ws[2]+ws[3])  * (1.f/128.f);
    float m2  = (ws2[0]+ws2[1]+ws2[2]+ws2[3]) * (1.f/128.f);
    float var = m2 - mu*mu;
    g_h[row*EMBED + tid] = ln_g[tid] * (y - mu) * rsqrtf(var + 1e-5f) + ln_b[tid];
}

// ---------------- CSR build: count / scan / fill ----------------
__global__ void k_count(const int* __restrict__ ei) {
    int idx = blockIdx.x * blockDim.x + threadIdx.x;   // 131072
    int b = idx >> 13, e = idx & (NEDGE-1);
    int dst = ei[b*2*NEDGE + NEDGE + e];
    atomicAdd(&g_cnt[b*SEQ + dst], 1);
}

__global__ void k_scan() {
    int b = blockIdx.x;            // 16
    int tid = threadIdx.x;         // 256, each handles 8 nodes
    __shared__ int sp[256];
    int base = b*SEQ + tid*8;
    int c[8];
    int tot = 0;
#pragma unroll
    for (int j = 0; j < 8; j++) { c[j] = g_cnt[base + j]; tot += c[j]; }
    sp[tid] = tot;
    __syncthreads();
    for (int o = 1; o < 256; o <<= 1) {
        int v = (tid >= o) ? sp[tid - o] : 0;
        __syncthreads();
        sp[tid] += v;
        __syncthreads();
    }
    int run = sp[tid] - tot;       // exclusive prefix
#pragma unroll
    for (int j = 0; j < 8; j++) { g_off[base + j] = run; run += c[j]; }
}

__global__ void k_fill(const int* __restrict__ ei) {
    int idx = blockIdx.x * blockDim.x + threadIdx.x;   // 131072
    int b = idx >> 13, e = idx & (NEDGE-1);
    const int* eb = ei + b*2*NEDGE;
    int src = eb[e];
    int dst = eb[NEDGE + e];
    int node = b*SEQ + dst;
    int pos = g_off[node] + atomicAdd(&g_cur[node], 1);
    g_srcs[b*NEDGE + pos] = src;
}

// ---------------- gather: hagg[node] = sum over incoming edges of h[src] ----------------
__global__ void k_gather() {
    int node = blockIdx.x * 8 + (threadIdx.x >> 5);    // 4096 blocks x 8 warps
    int lane = threadIdx.x & 31;
    int b = node >> 11;
    int start = g_off[node];
    int cnt   = g_cnt[node];
    const int* sp = g_srcs + b*NEDGE;
    float4 acc = make_float4(0.f, 0.f, 0.f, 0.f);
    for (int j = 0; j < cnt; j++) {
        int src = sp[start + j];
        float4 v = ((const float4*)(g_h + (b*SEQ + src)*EMBED))[lane];
        acc.x += v.x; acc.y += v.y; acc.z += v.z; acc.w += v.w;
    }
    ((float4*)(g_hagg + node*EMBED))[lane] = acc;
}

// ---------------- fused update GEMM + relu + mean-pool ----------------
// A = [h | hagg] (32768 x 256), W' = g_wT (256k x 256h). Each CTA: 64 rows x 256 cols.
__global__ __launch_bounds__(256, 2)
void k_updpool(const float* __restrict__ Wupd_b) {
    __shared__ float Ast[32][68];      // [k][row], padded
    __shared__ float Ws[32][256];      // [k][h]
    int r0 = blockIdx.x * 64;          // 512 blocks
    int b  = r0 >> 11;
    int tid = threadIdx.x;
    int ty = tid >> 5;                 // 0..7  (row group)
    int tx = tid & 31;                 // 0..31 (col group)
    float acc[8][8];
#pragma unroll
    for (int i = 0; i < 8; i++)
#pragma unroll
        for (int j = 0; j < 8; j++) acc[i][j] = 0.f;

    for (int kt = 0; kt < 256; kt += 32) {
        const float* Asrc = (kt < 128) ? (g_h + r0*EMBED + kt)
                                       : (g_hagg + r0*EMBED + (kt - 128));
#pragma unroll
        for (int it = 0; it < 2; it++) {
            int fid = tid + it*256;        // 0..511 float4s
            int r  = fid >> 3;
            int kq = fid & 7;
            float4 v = *(const float4*)(Asrc + r*EMBED + kq*4);
            Ast[kq*4+0][r] = v.x; Ast[kq*4+1][r] = v.y;
            Ast[kq*4+2][r] = v.z; Ast[kq*4+3][r] = v.w;
        }
#pragma unroll
        for (int it = 0; it < 8; it++) {
            int fid = tid + it*256;        // 0..2047 float4s
            int kk = fid >> 6;
            int hq = fid & 63;
            *(float4*)&Ws[kk][hq*4] = *(const float4*)(g_wT + (kt+kk)*256 + hq*4);
        }
        __syncthreads();
#pragma unroll
        for (int kk = 0; kk < 32; kk++) {
            float a[8], w[8];
            *(float4*)(a)   = *(const float4*)&Ast[kk][ty*8];
            *(float4*)(a+4) = *(const float4*)&Ast[kk][ty*8+4];
#pragma unroll
            for (int j = 0; j < 8; j++) w[j] = Ws[kk][tx + 32*j];
#pragma unroll
            for (int i = 0; i < 8; i++)
#pragma unroll
                for (int j = 0; j < 8; j++) acc[i][j] += a[i] * w[j];
        }
        __syncthreads();
    }
    // epilogue: bias, relu, sum rows, block-reduce, atomic to pooled
    float colsum[8];
#pragma unroll
    for (int j = 0; j < 8; j++) {
        float bias = Wupd_b[tx + 32*j];
        float s = 0.f;
#pragma unroll
        for (int i = 0; i < 8; i++) s += fmaxf(acc[i][j] + bias, 0.f);
        colsum[j] = s;
    }
    float* red = &Ws[0][0];
#pragma unroll
    for (int j = 0; j < 8; j++) red[ty*256 + tx + 32*j] = colsum[j];
    __syncthreads();
    if (ty == 0) {
#pragma unroll
        for (int j = 0; j < 8; j++) {
            int col = tx + 32*j;
            float s = 0.f;
#pragma unroll
            for (int g = 0; g < 8; g++) s += red[g*256 + col];
            atomicAdd(&g_pooled[b*HID + col], s);
        }
    }
}

// ---------------- classifier ----------------
__global__ void k_cls(const float* __restrict__ cls_w, const float* __restrict__ cls_b,
                      float* __restrict__ out) {
    int tid = threadIdx.x;
    if (tid >= B_SZ*NCLS) return;
    int b = tid / NCLS, c = tid % NCLS;
    float acc = 0.f;
    const float* p = g_pooled + b*HID;
    const float* w = cls_w + c*HID;
    for (int h = 0; h < HID; h++) acc += p[h] * w[h];
    out[b*NCLS + c] = cls_b[c] + acc * (1.f/(float)SEQ);
}

// ---------------- launch ----------------
extern "C" void kernel_launch(void* const* d_in, const int* in_sizes, int n_in,
                              void* d_out, int out_size) {
    const int*   tokens = (const int*)  d_in[0];
    // d_in[1] = lengths (unused by reference)
    const int*   ei     = (const int*)  d_in[2];
    const float* emb    = (const float*)d_in[3];
    const float* A_log  = (const float*)d_in[4];
    const float* B_w    = (const float*)d_in[5];
    const float* C_w    = (const float*)d_in[6];
    const float* Dskip  = (const float*)d_in[7];
    const float* ln_g   = (const float*)d_in[8];
    const float* ln_b   = (const float*)d_in[9];
    const float* Wmsg   = (const float*)d_in[10];
    const float* Wupd   = (const float*)d_in[11];
    const float* Wupd_b = (const float*)d_in[12];
    const float* cls_w  = (const float*)d_in[13];
    const float* cls_b  = (const float*)d_in[14];
    float* out = (float*)d_out;

    k_zero  <<<128, 256>>>();
    k_prep  <<<DSTATE, 128>>>(A_log);
    k_wcomb <<<256, 256>>>(Wupd, Wmsg);
    k_bproj <<<512, 256>>>(tokens, emb, B_w);
    k_conv  <<<B_SZ*DSTATE, 256>>>();
    k_yln   <<<NROW, 128>>>(tokens, emb, C_w, Dskip, ln_g, ln_b);
    k_count <<<512, 256>>>(ei);
    k_scan  <<<B_SZ, 256>>>();
    k_fill  <<<512, 256>>>(ei);
    k_gather<<<NROW/8, 256>>>();
    k_updpool<<<NROW/64, 256>>>(Wupd_b);
    k_cls   <<<1, 256>>>(cls_w, cls_b, out);
}

// round 8
// speedup vs baseline: 2.6888x; 1.9737x over previous
#include <cuda_runtime.h>
#include <cuda_bf16.h>
#include <cstdint>

#define B_SZ   16
#define SEQ    2048
#define EMBED  128
#define DSTATE 16
#define HID    256
#define NCLS   10
#define NEDGE  8192
#define KLEN   64
#define NROW   (B_SZ*SEQ)   // 32768

// ---------------- scratch (static device arrays; no allocation) ----------------
__device__ float g_bmat[B_SZ*DSTATE*SEQ];  // [b][d][t]
__device__ float g_conv[NROW*DSTATE];      // [b][t][d]
__device__ float g_h[NROW*EMBED];          // LN output
__device__ float g_hagg[NROW*EMBED];       // gathered msgs
__device__ float g_w[256*256];             // combined weight [h][k]
__device__ float g_K[DSTATE*KLEN];         // conv taps
__device__ float g_pooled[B_SZ*HID];       // pooled partials
__device__ int   g_cnt[NROW];
__device__ int   g_off[NROW];
__device__ int   g_cur[NROW];
__device__ int   g_srcs[B_SZ*NEDGE];

// ---------------- zero counters / accumulators ----------------
__global__ void k_zero() {
    int i = blockIdx.x * blockDim.x + threadIdx.x;   // 32768
    g_cnt[i] = 0;
    g_cur[i] = 0;
    if (i < B_SZ*HID) g_pooled[i] = 0.f;
}

// ---------------- conv taps ----------------
__global__ void k_prep(const float* __restrict__ A_log) {
    int d = blockIdx.x;
    int tid = threadIdx.x;         // 128
    float a = expf(-expf(A_log[tid*DSTATE + d]));
    float p = 1.f;
    __shared__ float ws[4];
    for (int tau = 0; tau < KLEN; tau++) {
        float s = p;
        for (int o = 16; o; o >>= 1) s += __shfl_down_sync(0xffffffffu, s, o);
        if ((tid & 31) == 0) ws[tid >> 5] = s;
        __syncthreads();
        if (tid == 0) g_K[d*KLEN + tau] = (ws[0]+ws[1]+ws[2]+ws[3]) * (1.f/128.f);
        __syncthreads();
        p *= a;
    }
}

// ---------------- combined weight: g_w[h][k] = [Wupd1 | Wupd2@Wmsg] ----------------
__global__ void k_wcomb(const float* __restrict__ Wupd_w, const float* __restrict__ Wmsg_w) {
    int h = blockIdx.x;     // 256
    int k = threadIdx.x;    // 256
    float v;
    if (k < 128) {
        v = Wupd_w[h*384 + k];
    } else {
        int d = k - 128;
        float acc = 0.f;
        const float* w2 = Wupd_w + h*384 + 128;
        for (int hp = 0; hp < 256; hp++) acc += w2[hp] * Wmsg_w[hp*128 + d];
        v = acc;
    }
    g_w[h*256 + k] = v;
}

// ---------------- B projection: warp per 4 rows ----------------
__global__ void k_bproj(const int* __restrict__ tokens, const float* __restrict__ emb,
                        const float* __restrict__ B_w) {
    int w = (blockIdx.x * blockDim.x + threadIdx.x) >> 5;   // 0..8191
    int lane = threadIdx.x & 31;
    int d = lane >> 1, kg = lane & 1;
    float4 wr[16];
    const float4* bw = (const float4*)(B_w + d*EMBED + kg*64);
#pragma unroll
    for (int i = 0; i < 16; i++) wr[i] = bw[i];
    int r0 = w * 4;
    int b = r0 >> 11, t0 = r0 & (SEQ-1);
    float vals[4];
#pragma unroll
    for (int j = 0; j < 4; j++) {
        int tok = tokens[r0 + j];
        const float4* xp = (const float4*)(emb + tok*EMBED + kg*64);
        float acc = 0.f;
#pragma unroll
        for (int i = 0; i < 16; i++) {
            float4 x = xp[i];
            acc += wr[i].x*x.x + wr[i].y*x.y + wr[i].z*x.z + wr[i].w*x.w;
        }
        acc += __shfl_xor_sync(0xffffffffu, acc, 1);
        vals[j] = acc;
    }
    if (kg == 0) {
        float* bp = g_bmat + (b*DSTATE + d)*SEQ + t0;
        *(float4*)bp = make_float4(vals[0], vals[1], vals[2], vals[3]);
    }
}

// ---------------- 64-tap causal convolution (smem-staged) ----------------
__global__ void k_conv() {
    int bd = blockIdx.x;           // 256 = B*DSTATE
    int b = bd >> 4, d = bd & 15;
    __shared__ float sb[SEQ];
    __shared__ float sK[KLEN];
    int tid = threadIdx.x;         // 256
    if (tid < KLEN) sK[tid] = g_K[d*KLEN + tid];
    const float4* bm4 = (const float4*)(g_bmat + bd*SEQ);
    float4* sb4 = (float4*)sb;
    for (int i = tid; i < SEQ/4; i += 256) sb4[i] = bm4[i];
    __syncthreads();
    for (int t0 = tid; t0 < SEQ; t0 += 256) {
        float acc = 0.f;
        int tmax = t0 < (KLEN-1) ? t0 : (KLEN-1);
        for (int tau = 0; tau <= tmax; tau++) acc += sK[tau] * sb[t0 - tau];
        g_conv[(b*SEQ + t0)*DSTATE + d] = acc;
    }
}

// ---------------- y = conv@C^T + D*emb[tok], LayerNorm; warp per row ----------------
__global__ void k_yln(const int* __restrict__ tokens, const float* __restrict__ emb,
                      const float* __restrict__ C_w, const float* __restrict__ Dskip,
                      const float* __restrict__ ln_g, const float* __restrict__ ln_b) {
    int row = blockIdx.x * 8 + (threadIdx.x >> 5);   // 4096 blocks x 8 warps
    int lane = threadIdx.x & 31;
    float cv = 0.f;
    if (lane < DSTATE) cv = g_conv[row*DSTATE + lane];
    float cd[16];
#pragma unroll
    for (int d = 0; d < 16; d++) cd[d] = __shfl_sync(0xffffffffu, cv, d);
    int tok = tokens[row];
    float4 xe = *(const float4*)(emb + tok*EMBED + lane*4);
    float4 dk = *(const float4*)(Dskip + lane*4);
    float y[4] = {dk.x*xe.x, dk.y*xe.y, dk.z*xe.z, dk.w*xe.w};
#pragma unroll
    for (int j = 0; j < 4; j++) {
        const float4* cw = (const float4*)(C_w + (lane*4 + j)*DSTATE);
        float4 c0 = cw[0], c1 = cw[1], c2 = cw[2], c3 = cw[3];
        y[j] += cd[0]*c0.x + cd[1]*c0.y + cd[2]*c0.z + cd[3]*c0.w
              + cd[4]*c1.x + cd[5]*c1.y + cd[6]*c1.z + cd[7]*c1.w
              + cd[8]*c2.x + cd[9]*c2.y + cd[10]*c2.z + cd[11]*c2.w
              + cd[12]*c3.x + cd[13]*c3.y + cd[14]*c3.z + cd[15]*c3.w;
    }
    float s  = y[0]+y[1]+y[2]+y[3];
    float s2 = y[0]*y[0]+y[1]*y[1]+y[2]*y[2]+y[3]*y[3];
    for (int o = 16; o; o >>= 1) {
        s  += __shfl_xor_sync(0xffffffffu, s,  o);
        s2 += __shfl_xor_sync(0xffffffffu, s2, o);
    }
    float mu  = s  * (1.f/128.f);
    float var = s2 * (1.f/128.f) - mu*mu;
    float r = rsqrtf(var + 1e-5f);
    float4 lg = *(const float4*)(ln_g + lane*4);
    float4 lb = *(const float4*)(ln_b + lane*4);
    float4 out;
    out.x = lg.x*(y[0]-mu)*r + lb.x;
    out.y = lg.y*(y[1]-mu)*r + lb.y;
    out.z = lg.z*(y[2]-mu)*r + lb.z;
    out.w = lg.w*(y[3]-mu)*r + lb.w;
    *(float4*)(g_h + row*EMBED + lane*4) = out;
}

// ---------------- CSR build ----------------
__global__ void k_count(const int* __restrict__ ei) {
    int idx = blockIdx.x * blockDim.x + threadIdx.x;
    int b = idx >> 13, e = idx & (NEDGE-1);
    int dst = ei[b*2*NEDGE + NEDGE + e];
    atomicAdd(&g_cnt[b*SEQ + dst], 1);
}

__global__ void k_scan() {
    int b = blockIdx.x;
    int tid = threadIdx.x;         // 256
    __shared__ int sp[256];
    int base = b*SEQ + tid*8;
    int c[8];
    int tot = 0;
#pragma unroll
    for (int j = 0; j < 8; j++) { c[j] = g_cnt[base + j]; tot += c[j]; }
    sp[tid] = tot;
    __syncthreads();
    for (int o = 1; o < 256; o <<= 1) {
        int v = (tid >= o) ? sp[tid - o] : 0;
        __syncthreads();
        sp[tid] += v;
        __syncthreads();
    }
    int run = sp[tid] - tot;
#pragma unroll
    for (int j = 0; j < 8; j++) { g_off[base + j] = run; run += c[j]; }
}

__global__ void k_fill(const int* __restrict__ ei) {
    int idx = blockIdx.x * blockDim.x + threadIdx.x;
    int b = idx >> 13, e = idx & (NEDGE-1);
    const int* eb = ei + b*2*NEDGE;
    int src = eb[e];
    int dst = eb[NEDGE + e];
    int node = b*SEQ + dst;
    int pos = g_off[node] + atomicAdd(&g_cur[node], 1);
    g_srcs[b*NEDGE + pos] = src;
}

// ---------------- gather ----------------
__global__ void k_gather() {
    int node = blockIdx.x * 8 + (threadIdx.x >> 5);
    int lane = threadIdx.x & 31;
    int b = node >> 11;
    int start = g_off[node];
    int cnt   = g_cnt[node];
    const int* sp = g_srcs + b*NEDGE;
    float4 acc = make_float4(0.f, 0.f, 0.f, 0.f);
    for (int j = 0; j < cnt; j++) {
        int src = sp[start + j];
        float4 v = ((const float4*)(g_h + (b*SEQ + src)*EMBED))[lane];
        acc.x += v.x; acc.y += v.y; acc.z += v.z; acc.w += v.w;
    }
    ((float4*)(g_hagg + node*EMBED))[lane] = acc;
}

// ================= mma.sync tf32 GEMM + relu + mean-pool =================
// C[32768x256] = [h|hagg][32768x256] @ g_w^T, then relu(+bias) and mean-pool.
// CTA tile 128M x 128N, K staged in 8 chunks of 32. grid = 512 (rowblk*2 + nhalf).
// smem layout [m][k], stride 36 words: fragment LDS banks = 4g+tg = 0..31, conflict-free.

__device__ __forceinline__ uint32_t to_tf32(float f) {
    uint32_t u;
    asm("cvt.rna.tf32.f32 %0, %1;" : "=r"(u) : "f"(f));
    return u;
}
__device__ __forceinline__ void mma_tf32(float* c, const uint32_t* a, const uint32_t* b) {
    asm volatile("mma.sync.aligned.m16n8k8.row.col.f32.tf32.tf32.f32 "
        "{%0,%1,%2,%3}, {%4,%5,%6,%7}, {%8,%9}, {%0,%1,%2,%3};"
        : "+f"(c[0]), "+f"(c[1]), "+f"(c[2]), "+f"(c[3])
        : "r"(a[0]), "r"(a[1]), "r"(a[2]), "r"(a[3]), "r"(b[0]), "r"(b[1]));
}

#define SSTRIDE 36

__global__ __launch_bounds__(256, 1)
void k_gemm(const float* __restrict__ Wupd_b) {
    __shared__ uint32_t sA[128*SSTRIDE];   // 18432 B
    __shared__ uint32_t sB[128*SSTRIDE];   // 18432 B
    __shared__ float sBias[256];

    int tid  = threadIdx.x;
    int wid  = tid >> 5;
    int lane = tid & 31;
    int g    = lane >> 2;       // 0..7
    int tg   = lane & 3;        // 0..3
    int rblk = blockIdx.x >> 1;
    int nb   = (blockIdx.x & 1) * 128;
    int r0   = rblk * 128;
    int b    = r0 >> 11;

    int wm = wid & 1;           // 2 M groups of 64
    int wn = wid >> 1;          // 4 N groups of 32
    int m0w = wm * 64;
    int n0w = wn * 32;

    if (tid < 256) sBias[tid] = Wupd_b[tid];

    float acc[4][4][4];
#pragma unroll
    for (int mi = 0; mi < 4; mi++)
#pragma unroll
        for (int ni = 0; ni < 4; ni++)
#pragma unroll
            for (int j = 0; j < 4; j++) acc[mi][ni][j] = 0.f;

    float4 pa[4], pb[4];
    // prefetch chunk 0
    {
        const float* Asrc = g_h + (size_t)r0*EMBED;
#pragma unroll
        for (int i = 0; i < 4; i++) {
            int idx = tid + i*256;
            int r = idx >> 3, q = idx & 7;
            pa[i] = *(const float4*)(Asrc + r*EMBED + q*4);
            pb[i] = *(const float4*)(g_w + (nb + r)*256 + q*4);
        }
    }

    for (int t = 0; t < 8; t++) {
        __syncthreads();
        // store staged chunk (with tf32 rounding)
#pragma unroll
        for (int i = 0; i < 4; i++) {
            int idx = tid + i*256;
            int r = idx >> 3, q = idx & 7;
            uint4 ua = make_uint4(to_tf32(pa[i].x), to_tf32(pa[i].y),
                                  to_tf32(pa[i].z), to_tf32(pa[i].w));
            uint4 ub = make_uint4(to_tf32(pb[i].x), to_tf32(pb[i].y),
                                  to_tf32(pb[i].z), to_tf32(pb[i].w));
            *(uint4*)&sA[r*SSTRIDE + q*4] = ua;
            *(uint4*)&sB[r*SSTRIDE + q*4] = ub;
        }
        __syncthreads();
        // prefetch next chunk
        if (t < 7) {
            int tn = t + 1;
            const float* Asrc = (tn < 4) ? (g_h    + (size_t)r0*EMBED + tn*32)
                                         : (g_hagg + (size_t)r0*EMBED + (tn-4)*32);
#pragma unroll
            for (int i = 0; i < 4; i++) {
                int idx = tid + i*256;
                int r = idx >> 3, q = idx & 7;
                pa[i] = *(const float4*)(Asrc + r*EMBED + q*4);
                pb[i] = *(const float4*)(g_w + (nb + r)*256 + tn*32 + q*4);
            }
        }
        // compute this chunk: 4 k-tiles of 8
#pragma unroll
        for (int kt = 0; kt < 4; kt++) {
            int kk = kt * 8;
            uint32_t af[4][4], bf[4][2];
#pragma unroll
            for (int mi = 0; mi < 4; mi++) {
                int rb = m0w + mi*16;
                const uint32_t* pm0 = sA + (rb + g    )*SSTRIDE + kk;
                const uint32_t* pm1 = sA + (rb + g + 8)*SSTRIDE + kk;
                af[mi][0] = pm0[tg];
                af[mi][1] = pm1[tg];
                af[mi][2] = pm0[tg + 4];
                af[mi][3] = pm1[tg + 4];
            }
#pragma unroll
            for (int ni = 0; ni < 4; ni++) {
                const uint32_t* pn = sB + (n0w + ni*8 + g)*SSTRIDE + kk;
                bf[ni][0] = pn[tg];
                bf[ni][1] = pn[tg + 4];
            }
#pragma unroll
            for (int mi = 0; mi < 4; mi++)
#pragma unroll
                for (int ni = 0; ni < 4; ni++)
                    mma_tf32(acc[mi][ni], af[mi], bf[ni]);
        }
    }

    // epilogue: bias + relu, sum over rows, reduce across g, atomic to pooled
#pragma unroll
    for (int ni = 0; ni < 4; ni++) {
        int col0 = nb + n0w + ni*8 + 2*tg;
        float b0 = sBias[col0], b1 = sBias[col0 + 1];
        float cs0 = 0.f, cs1 = 0.f;
#pragma unroll
        for (int mi = 0; mi < 4; mi++) {
            cs0 += fmaxf(acc[mi][ni][0] + b0, 0.f) + fmaxf(acc[mi][ni][2] + b0, 0.f);
            cs1 += fmaxf(acc[mi][ni][1] + b1, 0.f) + fmaxf(acc[mi][ni][3] + b1, 0.f);
        }
        // sum across g (lane bits 2..4)
#pragma unroll
        for (int o = 4; o <= 16; o <<= 1) {
            cs0 += __shfl_xor_sync(0xffffffffu, cs0, o);
            cs1 += __shfl_xor_sync(0xffffffffu, cs1, o);
        }
        if (g == 0) {
            atomicAdd(&g_pooled[b*HID + col0],     cs0);
            atomicAdd(&g_pooled[b*HID + col0 + 1], cs1);
        }
    }
}

// ---------------- classifier ----------------
__global__ void k_cls(const float* __restrict__ cls_w, const float* __restrict__ cls_b,
                      float* __restrict__ out) {
    int tid = threadIdx.x;
    if (tid >= B_SZ*NCLS) return;
    int b = tid / NCLS, c = tid % NCLS;
    float acc = 0.f;
    const float* pp = g_pooled + b*HID;
    const float* w = cls_w + c*HID;
    for (int h = 0; h < HID; h++) acc += pp[h] * w[h];
    out[b*NCLS + c] = cls_b[c] + acc * (1.f/(float)SEQ);
}

// ---------------- launch ----------------
extern "C" void kernel_launch(void* const* d_in, const int* in_sizes, int n_in,
                              void* d_out, int out_size) {
    const int*   tokens = (const int*)  d_in[0];
    const int*   ei     = (const int*)  d_in[2];
    const float* emb    = (const float*)d_in[3];
    const float* A_log  = (const float*)d_in[4];
    const float* B_w    = (const float*)d_in[5];
    const float* C_w    = (const float*)d_in[6];
    const float* Dskip  = (const float*)d_in[7];
    const float* ln_g   = (const float*)d_in[8];
    const float* ln_b   = (const float*)d_in[9];
    const float* Wmsg   = (const float*)d_in[10];
    const float* Wupd   = (const float*)d_in[11];
    const float* Wupd_b = (const float*)d_in[12];
    const float* cls_w  = (const float*)d_in[13];
    const float* cls_b  = (const float*)d_in[14];
    float* out = (float*)d_out;

    k_zero  <<<128, 256>>>();
    k_prep  <<<DSTATE, 128>>>(A_log);
    k_wcomb <<<256, 256>>>(Wupd, Wmsg);
    k_bproj <<<1024, 256>>>(tokens, emb, B_w);
    k_conv  <<<B_SZ*DSTATE, 256>>>();
    k_yln   <<<NROW/8, 256>>>(tokens, emb, C_w, Dskip, ln_g, ln_b);
    k_count <<<512, 256>>>(ei);
    k_scan  <<<B_SZ, 256>>>();
    k_fill  <<<512, 256>>>(ei);
    k_gather<<<NROW/8, 256>>>();
    k_gemm  <<<(NROW/128)*2, 256>>>(Wupd_b);
    k_cls   <<<1, 256>>>(cls_w, cls_b, out);
}